// round 16
// baseline (speedup 1.0000x reference)
#include <cuda_runtime.h>
#include <cuda_fp16.h>
#include <math.h>

#define N_IMG 2
#define CCH   256
#define HH    256
#define WW    256
#define PHB   7
#define PWB   7
#define NBINS (PHB * PWB)
#define NPHASE (NBINS * 2)
#define NROIS 1024
#define SCALE 0.25f
#define CBLK  128                 // channels per gather block
#define GITEMS (NROIS * 2)        // gather work items (roi, channel-half)
#define TBLKS  4096               // transpose blocks per image (512 x 8)

// 64 MB static scratch: NHWC features in fp16 (L2-resident working set).
__device__ uint4 g_nhwc_h[(size_t)N_IMG * HH * WW * CCH / 8];

// ---------------------------------------------------------------------------
// Transpose body: one 32c x 128hw tile of image n, NCHW fp32 -> NHWC fp16.
// __ldcs input reads keep the streaming read from evicting NHWC from L2.
// ---------------------------------------------------------------------------
__device__ __forceinline__ void transpose_body(const float* __restrict__ in,
                                               int bx, int n, int t)
{
    __shared__ float4 tile[128 * 8];
    const int hw0 = (bx & 511) * 128;
    const int c0  = (bx >> 9) * 32;

    const float* src = in + (size_t)n * CCH * HH * WW;
    __half*      dst = (__half*)g_nhwc_h + (size_t)n * HH * WW * CCH;

    const int hw4 = t & 31;
    const int c4w = t >> 5;

    float vv[4][4];
#pragma unroll
    for (int j = 0; j < 4; ++j) {
        float4 ld = __ldcs((const float4*)(src + (size_t)(c0 + c4w * 4 + j) * (HH * WW)
                                               + hw0 + hw4 * 4));
        vv[j][0] = ld.x; vv[j][1] = ld.y; vv[j][2] = ld.z; vv[j][3] = ld.w;
    }
#pragma unroll
    for (int r = 0; r < 4; ++r) {
        float4 o = make_float4(vv[0][r], vv[1][r], vv[2][r], vv[3][r]);
        const int hw = hw4 * 4 + r;
        tile[hw * 8 + (c4w ^ ((hw >> 2) & 7))] = o;
    }
    __syncthreads();

#pragma unroll
    for (int k = 0; k < 2; ++k) {
        const int idx = t + k * 256;       // 0..511
        const int cq  = idx & 3;           // 8-channel group
        const int hw  = idx >> 2;
        const int sw  = (hw >> 2) & 7;
        float4 f0 = tile[hw * 8 + ((2 * cq)     ^ sw)];
        float4 f1 = tile[hw * 8 + ((2 * cq + 1) ^ sw)];
        __half2 h[4];
        h[0] = __floats2half2_rn(f0.x, f0.y);
        h[1] = __floats2half2_rn(f0.z, f0.w);
        h[2] = __floats2half2_rn(f1.x, f1.y);
        h[3] = __floats2half2_rn(f1.z, f1.w);
        *(uint4*)(dst + (size_t)(hw0 + hw) * CCH + c0 + cq * 8) = *(uint4*)h;
    }
}

// ---------------------------------------------------------------------------
// Gather body (proven R14/R15 config): one (roi, channel-half) item.
// Processes the item only if the roi's batch index == want_b.
// Stage A hoists per-(bin,phase) indices + fp16 weights; Stage B does 8-deep
// load batches with HFMA2 chains of 4 widened into fp32; fp16 smem staging;
// coalesced streaming flush.
// ---------------------------------------------------------------------------
__device__ __forceinline__ void gather_body(int item,
                                            const float* __restrict__ rois,
                                            float* __restrict__ out,
                                            int want_b, int tid)
{
    __shared__ uint2   s_outh[(CBLK / 4) * NBINS];  // 12544 B
    __shared__ int     s_idx[NPHASE * 8];           // 3136 B
    __shared__ __half2 s_wh [NPHASE * 8];           // 1568 B

    const int roi = item >> 1;
    const int c0  = (item & 1) * CBLK;

    const float* r = rois + roi * 6;
    const int b = (int)r[0];
    if (b != want_b) return;   // uniform across block; no barrier crossed

    const int cgrp   = tid & 31;
    const int bslice = tid >> 5;

    // ---- Stage A: per-(bin,phase) precompute by 98 threads ----
    if (tid < NPHASE) {
        const int bin = tid >> 1;
        const int sp  = tid & 1;
        const int ph  = bin / PWB;
        const int pw  = bin - ph * PWB;

        const float cx = fmaf(r[1], SCALE, -0.5f);
        const float cy = fmaf(r[2], SCALE, -0.5f);
        const float rw = r[3] * SCALE;
        const float rh = r[4] * SCALE;
        float sn, cs;
        sincosf(r[5], &sn, &cs);

        const float bin_h = rh * (1.0f / PHB);
        const float bin_w = rw * (1.0f / PWB);
        const float yy = -0.5f * rh + ((float)ph + ((float)sp + 0.5f) * 0.5f) * bin_h;

#pragma unroll
        for (int ix = 0; ix < 2; ++ix) {
            const float xx = -0.5f * rw + ((float)pw + ((float)ix + 0.5f) * 0.5f) * bin_w;
            float y = yy * cs - xx * sn + cy;
            float x = yy * sn + xx * cs + cx;

            const bool valid = (y > -1.0f) & (y < (float)HH) &
                               (x > -1.0f) & (x < (float)WW);
            y = fmaxf(y, 0.0f);
            x = fmaxf(x, 0.0f);

            int yl = (int)y;
            int xl = (int)x;
            int yh, xh; float ly, lx;
            if (yl >= HH - 1) { yl = HH - 1; yh = HH - 1; ly = 0.f; }
            else              { yh = yl + 1; ly = y - (float)yl; }
            if (xl >= WW - 1) { xl = WW - 1; xh = WW - 1; lx = 0.f; }
            else              { xh = xl + 1; lx = x - (float)xl; }

            const float vsc = valid ? 0.25f : 0.0f;   // folds the /4 mean
            const float hy = 1.f - ly, hx = 1.f - lx;
            const int base = tid * 8 + ix * 4;
            s_wh[base + 0] = __float2half2_rn(hy * hx * vsc);
            s_wh[base + 1] = __float2half2_rn(hy * lx * vsc);
            s_wh[base + 2] = __float2half2_rn(ly * hx * vsc);
            s_wh[base + 3] = __float2half2_rn(ly * lx * vsc);

            const int rl = yl * WW, rh2 = yh * WW;
            s_idx[base + 0] = (rl  + xl) << 6;   // * (CCH/4) uint2 units
            s_idx[base + 1] = (rl  + xh) << 6;
            s_idx[base + 2] = (rh2 + xl) << 6;
            s_idx[base + 3] = (rh2 + xh) << 6;
        }
    }
    __syncthreads();

    const uint2* __restrict__ feat =
        (const uint2*)g_nhwc_h + (size_t)b * (HH * WW * (CCH / 4))
        + (c0 / 4) + cgrp;

    // ---- Stage B: 8-deep load batches; HFMA2 chains of 4, fp32 widen ----
    for (int bin = bslice; bin < NBINS; bin += 8) {
        float2 a01 = make_float2(0.f, 0.f);
        float2 a23 = make_float2(0.f, 0.f);

#pragma unroll
        for (int sp = 0; sp < 2; ++sp) {
            const int base = (bin * 2 + sp) * 8;
            const int4  i01 = *(const int4*)&s_idx[base];
            const int4  i23 = *(const int4*)&s_idx[base + 4];
            uint4 wr0 = *(const uint4*)&s_wh[base];
            uint4 wr1 = *(const uint4*)&s_wh[base + 4];
            const __half2* w2a = (const __half2*)&wr0;
            const __half2* w2b = (const __half2*)&wr1;

            uint2 v[8];
            v[0] = __ldg(feat + i01.x);
            v[1] = __ldg(feat + i01.y);
            v[2] = __ldg(feat + i01.z);
            v[3] = __ldg(feat + i01.w);
            v[4] = __ldg(feat + i23.x);
            v[5] = __ldg(feat + i23.y);
            v[6] = __ldg(feat + i23.z);
            v[7] = __ldg(feat + i23.w);

            __half2 cl = __float2half2_rn(0.f);
            __half2 ch = __float2half2_rn(0.f);
#pragma unroll
            for (int i = 0; i < 4; ++i) {
                const __half2* hp = (const __half2*)&v[i];
                cl = __hfma2(w2a[i], hp[0], cl);
                ch = __hfma2(w2a[i], hp[1], ch);
            }
            {
                float2 fl = __half22float2(cl);
                float2 fh = __half22float2(ch);
                a01.x += fl.x; a01.y += fl.y;
                a23.x += fh.x; a23.y += fh.y;
            }
            cl = __float2half2_rn(0.f);
            ch = __float2half2_rn(0.f);
#pragma unroll
            for (int i = 0; i < 4; ++i) {
                const __half2* hp = (const __half2*)&v[4 + i];
                cl = __hfma2(w2b[i], hp[0], cl);
                ch = __hfma2(w2b[i], hp[1], ch);
            }
            {
                float2 fl = __half22float2(cl);
                float2 fh = __half22float2(ch);
                a01.x += fl.x; a01.y += fl.y;
                a23.x += fh.x; a23.y += fh.y;
            }
        }

        __half2 o2[2];
        o2[0] = __floats2half2_rn(a01.x, a01.y);
        o2[1] = __floats2half2_rn(a23.x, a23.y);
        s_outh[cgrp * NBINS + bin] = *(uint2*)o2;
    }

    __syncthreads();
    float* o = out + (size_t)roi * (CCH * NBINS) + (size_t)c0 * NBINS;
    for (int i = tid; i < (CBLK / 4) * NBINS; i += 256) {
        const int g   = i / NBINS;
        const int bb  = i - g * NBINS;
        uint2 raw = s_outh[i];
        const __half2* hp = (const __half2*)&raw;
        float2 f0 = __half22float2(hp[0]);
        float2 f1 = __half22float2(hp[1]);
        float* og = o + (4 * g) * NBINS + bb;
        __stcs(og + 0 * NBINS, f0.x);
        __stcs(og + 1 * NBINS, f0.y);
        __stcs(og + 2 * NBINS, f1.x);
        __stcs(og + 3 * NBINS, f1.y);
    }
}

// ---------------------------------------------------------------------------
// K1: transpose image 0 only.
// ---------------------------------------------------------------------------
__global__ void __launch_bounds__(256) k1_transpose_img0(const float* __restrict__ in)
{
    transpose_body(in, blockIdx.x, 0, threadIdx.x);
}

// ---------------------------------------------------------------------------
// K2 (fused): blocks 0..2047 gather b==0 rois (image 0 is ready); blocks
// 2048..6143 transpose image 1. Complementary bottlenecks co-scheduled.
// ---------------------------------------------------------------------------
__global__ void __launch_bounds__(256, 6) k2_fused(const float* __restrict__ in,
                                                   const float* __restrict__ rois,
                                                   float* __restrict__ out)
{
    if (blockIdx.x < GITEMS) {
        gather_body(blockIdx.x, rois, out, 0, threadIdx.x);
    } else {
        transpose_body(in, blockIdx.x - GITEMS, 1, threadIdx.x);
    }
}

// ---------------------------------------------------------------------------
// K3: gather b==1 rois (image 1 now ready).
// ---------------------------------------------------------------------------
__global__ void __launch_bounds__(256, 6) k3_gather_b1(const float* __restrict__ rois,
                                                       float* __restrict__ out)
{
    gather_body(blockIdx.x, rois, out, 1, threadIdx.x);
}

extern "C" void kernel_launch(void* const* d_in, const int* in_sizes, int n_in,
                              void* d_out, int out_size)
{
    const float* feat = (const float*)d_in[0];
    const float* rois = (const float*)d_in[1];
    if (in_sizes[0] == NROIS * 6) {
        rois = (const float*)d_in[0];
        feat = (const float*)d_in[1];
    }
    float* out = (float*)d_out;

    k1_transpose_img0<<<TBLKS, 256>>>(feat);
    k2_fused<<<GITEMS + TBLKS, 256>>>(feat, rois, out);
    k3_gather_b1<<<GITEMS, 256>>>(rois, out);
}

// round 17
// speedup vs baseline: 1.1506x; 1.1506x over previous
#include <cuda_runtime.h>
#include <cuda_fp16.h>
#include <math.h>

#define N_IMG 2
#define CCH   256
#define HH    256
#define WW    256
#define PHB   7
#define PWB   7
#define NBINS (PHB * PWB)
#define NPHASE (NBINS * 2)
#define NROIS 1024
#define SCALE 0.25f
#define CBLK  128                 // channels per gather block

// 64 MB static scratch: NHWC features in fp16 (L2-resident working set).
__device__ uint4 g_nhwc_h[(size_t)N_IMG * HH * WW * CCH / 8];

// ---------------------------------------------------------------------------
// Kernel 1: NCHW fp32 -> NHWC fp16 transpose (single 8192-block grid — the
// R16 split showed small grids lose DRAM efficiency). __ldcs input reads
// keep the streaming read from evicting the NHWC cache from L2.
// ---------------------------------------------------------------------------
__global__ void __launch_bounds__(256) nchw_to_nhwc_h_kernel(const float* __restrict__ in)
{
    __shared__ float4 tile[128 * 8];
    const int n   = blockIdx.z;
    const int hw0 = blockIdx.x * 128;
    const int c0  = blockIdx.y * 32;
    const int t   = threadIdx.x;

    const float* src = in + (size_t)n * CCH * HH * WW;
    __half*      dst = (__half*)g_nhwc_h + (size_t)n * HH * WW * CCH;

    const int hw4 = t & 31;
    const int c4w = t >> 5;

    float vv[4][4];
#pragma unroll
    for (int j = 0; j < 4; ++j) {
        float4 ld = __ldcs((const float4*)(src + (size_t)(c0 + c4w * 4 + j) * (HH * WW)
                                               + hw0 + hw4 * 4));
        vv[j][0] = ld.x; vv[j][1] = ld.y; vv[j][2] = ld.z; vv[j][3] = ld.w;
    }
#pragma unroll
    for (int r = 0; r < 4; ++r) {
        float4 o = make_float4(vv[0][r], vv[1][r], vv[2][r], vv[3][r]);
        const int hw = hw4 * 4 + r;
        tile[hw * 8 + (c4w ^ ((hw >> 2) & 7))] = o;
    }
    __syncthreads();

#pragma unroll
    for (int k = 0; k < 2; ++k) {
        const int idx = t + k * 256;       // 0..511
        const int cq  = idx & 3;           // 8-channel group
        const int hw  = idx >> 2;
        const int sw  = (hw >> 2) & 7;
        float4 f0 = tile[hw * 8 + ((2 * cq)     ^ sw)];
        float4 f1 = tile[hw * 8 + ((2 * cq + 1) ^ sw)];
        __half2 h[4];
        h[0] = __floats2half2_rn(f0.x, f0.y);
        h[1] = __floats2half2_rn(f0.z, f0.w);
        h[2] = __floats2half2_rn(f1.x, f1.y);
        h[3] = __floats2half2_rn(f1.z, f1.w);
        *(uint4*)(dst + (size_t)(hw0 + hw) * CCH + c0 + cq * 8) = *(uint4*)h;
    }
}

// ---------------------------------------------------------------------------
// Kernel 2: rotated RoIAlign gather on fp16 NHWC features. Block =
// (roi, channel-half): 128 channels, 256 threads = 32 uint2-groups x 8
// bin-slices. Stage A hoists per-(bin,phase) indices + fp16 weights.
// Stage B: per-phase 8-deep load batches; 4 INDEPENDENT HFMA2 accumulators
// per phase (corners round-robin -> dependent ops 4 issue slots apart =
// HFMA2 latency covered, no pipeline bubbles), combined with hadd2 and
// widened into fp32 per phase. fp16 smem staging; coalesced streaming flush.
// ---------------------------------------------------------------------------
__global__ void __launch_bounds__(256, 6) roialign_rot_kernel(
    const float* __restrict__ rois, float* __restrict__ out)
{
    __shared__ uint2   s_outh[(CBLK / 4) * NBINS];  // 12544 B
    __shared__ int     s_idx[NPHASE * 8];           // 3136 B
    __shared__ __half2 s_wh [NPHASE * 8];           // 1568 B

    const int roi    = blockIdx.x;
    const int c0     = blockIdx.y * CBLK;      // 0 or 128
    const int tid    = threadIdx.x;
    const int cgrp   = tid & 31;               // uint2 channel group (4 halves)
    const int bslice = tid >> 5;               // 0..7

    const float* r = rois + roi * 6;
    const int b = (int)r[0];

    // ---- Stage A: per-(bin,phase) precompute by 98 threads ----
    if (tid < NPHASE) {
        const int bin = tid >> 1;
        const int sp  = tid & 1;
        const int ph  = bin / PWB;
        const int pw  = bin - ph * PWB;

        const float cx = fmaf(r[1], SCALE, -0.5f);
        const float cy = fmaf(r[2], SCALE, -0.5f);
        const float rw = r[3] * SCALE;
        const float rh = r[4] * SCALE;
        float sn, cs;
        sincosf(r[5], &sn, &cs);

        const float bin_h = rh * (1.0f / PHB);
        const float bin_w = rw * (1.0f / PWB);
        const float yy = -0.5f * rh + ((float)ph + ((float)sp + 0.5f) * 0.5f) * bin_h;

#pragma unroll
        for (int ix = 0; ix < 2; ++ix) {
            const float xx = -0.5f * rw + ((float)pw + ((float)ix + 0.5f) * 0.5f) * bin_w;
            float y = yy * cs - xx * sn + cy;
            float x = yy * sn + xx * cs + cx;

            const bool valid = (y > -1.0f) & (y < (float)HH) &
                               (x > -1.0f) & (x < (float)WW);
            y = fmaxf(y, 0.0f);
            x = fmaxf(x, 0.0f);

            int yl = (int)y;
            int xl = (int)x;
            int yh, xh; float ly, lx;
            if (yl >= HH - 1) { yl = HH - 1; yh = HH - 1; ly = 0.f; }
            else              { yh = yl + 1; ly = y - (float)yl; }
            if (xl >= WW - 1) { xl = WW - 1; xh = WW - 1; lx = 0.f; }
            else              { xh = xl + 1; lx = x - (float)xl; }

            const float vsc = valid ? 0.25f : 0.0f;   // folds the /4 mean
            const float hy = 1.f - ly, hx = 1.f - lx;
            const int base = tid * 8 + ix * 4;
            s_wh[base + 0] = __float2half2_rn(hy * hx * vsc);
            s_wh[base + 1] = __float2half2_rn(hy * lx * vsc);
            s_wh[base + 2] = __float2half2_rn(ly * hx * vsc);
            s_wh[base + 3] = __float2half2_rn(ly * lx * vsc);

            const int rl = yl * WW, rh2 = yh * WW;
            s_idx[base + 0] = (rl  + xl) << 6;   // * (CCH/4) uint2 units
            s_idx[base + 1] = (rl  + xh) << 6;
            s_idx[base + 2] = (rh2 + xl) << 6;
            s_idx[base + 3] = (rh2 + xh) << 6;
        }
    }
    __syncthreads();

    const uint2* __restrict__ feat =
        (const uint2*)g_nhwc_h + (size_t)b * (HH * WW * (CCH / 4))
        + (c0 / 4) + cgrp;

    // ---- Stage B: 8-deep load batches; 4-way HFMA2, fp32 widen/phase ----
    for (int bin = bslice; bin < NBINS; bin += 8) {
        float2 a01 = make_float2(0.f, 0.f);
        float2 a23 = make_float2(0.f, 0.f);

#pragma unroll
        for (int sp = 0; sp < 2; ++sp) {
            const int base = (bin * 2 + sp) * 8;
            const int4  i01 = *(const int4*)&s_idx[base];
            const int4  i23 = *(const int4*)&s_idx[base + 4];
            uint4 wr0 = *(const uint4*)&s_wh[base];
            uint4 wr1 = *(const uint4*)&s_wh[base + 4];
            const __half2* w2a = (const __half2*)&wr0;
            const __half2* w2b = (const __half2*)&wr1;

            uint2 v[8];
            v[0] = __ldg(feat + i01.x);
            v[1] = __ldg(feat + i01.y);
            v[2] = __ldg(feat + i01.z);
            v[3] = __ldg(feat + i01.w);
            v[4] = __ldg(feat + i23.x);
            v[5] = __ldg(feat + i23.y);
            v[6] = __ldg(feat + i23.z);
            v[7] = __ldg(feat + i23.w);

            // 4 independent accumulators: even corners -> c0, odd -> c1.
            // Dependent HFMA2s are 4 issue slots apart (latency covered).
            __half2 c0l = __float2half2_rn(0.f), c0h = c0l;
            __half2 c1l = c0l,                   c1h = c0l;
#pragma unroll
            for (int i = 0; i < 4; ++i) {
                const __half2 wA = (i < 2) ? w2a[2 * i]     : w2b[2 * (i - 2)];
                const __half2 wB = (i < 2) ? w2a[2 * i + 1] : w2b[2 * (i - 2) + 1];
                const __half2* hp = (const __half2*)&v[2 * i];
                const __half2* hq = (const __half2*)&v[2 * i + 1];
                c0l = __hfma2(wA, hp[0], c0l);
                c0h = __hfma2(wA, hp[1], c0h);
                c1l = __hfma2(wB, hq[0], c1l);
                c1h = __hfma2(wB, hq[1], c1h);
            }
            const __half2 cl = __hadd2(c0l, c1l);
            const __half2 ch = __hadd2(c0h, c1h);
            const float2 fl = __half22float2(cl);
            const float2 fh = __half22float2(ch);
            a01.x += fl.x; a01.y += fl.y;
            a23.x += fh.x; a23.y += fh.y;
        }

        // fp16 staging: one STS.64 per bin, conflict-free per half-warp.
        __half2 o2[2];
        o2[0] = __floats2half2_rn(a01.x, a01.y);
        o2[1] = __floats2half2_rn(a23.x, a23.y);
        s_outh[cgrp * NBINS + bin] = *(uint2*)o2;
    }

    __syncthreads();
    // Flush: LDS.64 per entry, convert to fp32, 4 coalesced scalar
    // streaming stores (output written once, never re-read).
    float* o = out + (size_t)roi * (CCH * NBINS) + (size_t)c0 * NBINS;
    for (int i = tid; i < (CBLK / 4) * NBINS; i += 256) {
        const int g   = i / NBINS;       // channel quad
        const int bb  = i - g * NBINS;   // bin
        uint2 raw = s_outh[i];
        const __half2* hp = (const __half2*)&raw;
        float2 f0 = __half22float2(hp[0]);
        float2 f1 = __half22float2(hp[1]);
        float* og = o + (4 * g) * NBINS + bb;
        __stcs(og + 0 * NBINS, f0.x);
        __stcs(og + 1 * NBINS, f0.y);
        __stcs(og + 2 * NBINS, f1.x);
        __stcs(og + 3 * NBINS, f1.y);
    }
}

extern "C" void kernel_launch(void* const* d_in, const int* in_sizes, int n_in,
                              void* d_out, int out_size)
{
    const float* feat = (const float*)d_in[0];
    const float* rois = (const float*)d_in[1];
    if (in_sizes[0] == NROIS * 6) {
        rois = (const float*)d_in[0];
        feat = (const float*)d_in[1];
    }
    float* out = (float*)d_out;

    dim3 tg((HH * WW) / 128, CCH / 32, N_IMG);
    nchw_to_nhwc_h_kernel<<<tg, 256>>>(feat);

    dim3 gg(NROIS, CCH / CBLK, 1);
    roialign_rot_kernel<<<gg, 256>>>(rois, out);
}